// round 11
// baseline (speedup 1.0000x reference)
#include <cuda_runtime.h>
#include <stdint.h>

#define HH 512
#define WW 512
#define NB 2
#define NC 4
#define NCL 3                 // classes 1..3 only (class 0 masked by reference)
#define NPRES (NB*NCL)
#define NBLK 256
#define NTHR 256

// Interleaved scratch: per pixel one uint = gp (low 16) | gn (high 16),
// for classes 1..3 only. 2*3*512*512*4 B = 6.3 MB (L2-resident).
__device__ __align__(16) unsigned int gpn_buf[(size_t)NB*NCL*HH*WW];
__device__ double g_acc;            // static-init 0; reset by finalize block
__device__ unsigned int g_count;    // static-init 0; reset by finalize block
__device__ unsigned int g_bar;      // static-init 0; reset by finalize block
__device__ int g_present[NPRES];    // static-init 0; reset by finalize block

// ---------------------------------------------------------------------------
// ONE persistent kernel, 256 blocks x 256 threads (>=2 blocks/SM guaranteed by
// launch_bounds(256,2): regs<=128, smem 37KB -> all 256 blocks co-resident,
// so the software grid barrier cannot deadlock).
//
// Phase 1 (per block: 4 rows): row EDT. Warps 0-2 forward scan classes 1-3,
//   warps 3-5 backward scan; combine; coalesced uint4 write-out.
//   Inline dtype probe: int64 labels (0..3) have all odd 32-bit words zero.
// Grid barrier (atomic arrive + spin + fences).
// Phase 2 (per block: 2 tiles of 2 rows x 512 cols): load rows r0-2..r0+3 of
//   all 3 classes into smem (36KB, coalesced); center + d=1,2 probes from
//   shared memory; rare d>=3 tail from gmem; fused softmax + reduction.
// Finalize: last block writes out and resets all device state (graph replay).
// ---------------------------------------------------------------------------
__global__ void __launch_bounds__(NTHR, 2) fused_kernel(
        const float* __restrict__ logits,
        const int* __restrict__ tgt_words,
        float* __restrict__ out) {
    __shared__ __align__(16) unsigned char raw[36864];
    __shared__ double warp_sums[8];
    __shared__ bool is_last;

    const int tid = threadIdx.x;
    const int bid = blockIdx.x;
    const int warp = tid >> 5;
    const int lane = tid & 31;
    const unsigned FULL = 0xffffffffu;

    // ===================== Phase 1: row EDT (4 rows per block) ==============
    {
        unsigned char* cls = (unsigned char*)raw;                          // 512 B
        unsigned short (*dfp)[WW] = (unsigned short(*)[WW])(raw + 512);    // 3 KB
        unsigned short (*dfn)[WW] = (unsigned short(*)[WW])(raw + 3584);
        unsigned short (*dbp)[WW] = (unsigned short(*)[WW])(raw + 6656);
        unsigned short (*dbn)[WW] = (unsigned short(*)[WW])(raw + 9728);
        ushort2 (*gstage)[WW] = (ushort2(*)[WW])(raw + 12800);             // 3 KB

        #pragma unroll 1
        for (int rk = 0; rk < 4; rk++) {
            const int rid = bid * 4 + rk;        // 0..1023
            const int n = rid >> 9;
            const int r = rid & (HH - 1);
            const size_t elem_base = ((size_t)n * HH + r) * WW;

            int4 v; int myodd = 0;
            if (tid < 128) {
                v = reinterpret_cast<const int4*>(tgt_words + elem_base)[tid];
                myodd = v.y | v.w;
            }
            if (__syncthreads_or(myodd)) {
                if (tid < 128) {
                    cls[4*tid+0] = (unsigned char)v.x;
                    cls[4*tid+1] = (unsigned char)v.y;
                    cls[4*tid+2] = (unsigned char)v.z;
                    cls[4*tid+3] = (unsigned char)v.w;
                }
            } else {
                if (tid < 128) {
                    const longlong4 q = reinterpret_cast<const longlong4*>(
                        tgt_words + 2 * elem_base)[tid];
                    cls[4*tid+0] = (unsigned char)q.x;
                    cls[4*tid+1] = (unsigned char)q.y;
                    cls[4*tid+2] = (unsigned char)q.z;
                    cls[4*tid+3] = (unsigned char)q.w;
                }
            }
            __syncthreads();

            const int KBIG = 1 << 20;
            const int SINF = 1 << 26;
            if (warp < NCL) {
                // forward (left-to-right), class = warp+1
                const unsigned char cc = (unsigned char)(warp + 1);
                unsigned char cl[16];
                int dp = KBIG, dn = KBIG;
                bool found = false;
                #pragma unroll
                for (int i = 0; i < 16; i++) {
                    cl[i] = cls[lane * 16 + i];
                    bool m = (cl[i] == cc);
                    found |= m;
                    dp = m ? dp + 1 : 0;
                    dn = m ? 0 : dn + 1;
                }
                int sp = (dp >= KBIG) ? SINF : dp;
                int sn = (dn >= KBIG) ? SINF : dn;
                #pragma unroll
                for (int off = 1; off < 32; off <<= 1) {
                    int up_p = __shfl_up_sync(FULL, sp, off);
                    int up_n = __shfl_up_sync(FULL, sn, off);
                    if (lane >= off) {
                        sp = min(up_p + 16 * off, sp);
                        sn = min(up_n + 16 * off, sn);
                    }
                }
                int ep = __shfl_up_sync(FULL, sp, 1);
                int en = __shfl_up_sync(FULL, sn, 1);
                int carp = (lane == 0) ? 1000000 : min(1000000 + 16 * lane, ep);
                int carn = (lane == 0) ? 1000000 : min(1000000 + 16 * lane, en);
                #pragma unroll
                for (int i = 0; i < 16; i++) {
                    bool m = (cl[i] == cc);
                    carp = m ? carp + 1 : 0;
                    carn = m ? 0 : carn + 1;
                    dfp[warp][lane * 16 + i] = (unsigned short)min(carp, 60000);
                    dfn[warp][lane * 16 + i] = (unsigned short)min(carn, 60000);
                }
                if (__any_sync(FULL, found) && lane == 0)
                    atomicOr(&g_present[n * NCL + warp], 1);
            } else if (warp < 2 * NCL) {
                // backward (right-to-left), class = warp-2
                const int c = warp - NCL;
                const unsigned char cc = (unsigned char)(c + 1);
                unsigned char cl[16];
                int dp = KBIG, dn = KBIG;
                #pragma unroll
                for (int i = 0; i < 16; i++) {
                    cl[i] = cls[WW - 1 - lane * 16 - i];
                    bool m = (cl[i] == cc);
                    dp = m ? dp + 1 : 0;
                    dn = m ? 0 : dn + 1;
                }
                int sp = (dp >= KBIG) ? SINF : dp;
                int sn = (dn >= KBIG) ? SINF : dn;
                #pragma unroll
                for (int off = 1; off < 32; off <<= 1) {
                    int up_p = __shfl_up_sync(FULL, sp, off);
                    int up_n = __shfl_up_sync(FULL, sn, off);
                    if (lane >= off) {
                        sp = min(up_p + 16 * off, sp);
                        sn = min(up_n + 16 * off, sn);
                    }
                }
                int ep = __shfl_up_sync(FULL, sp, 1);
                int en = __shfl_up_sync(FULL, sn, 1);
                int carp = (lane == 0) ? 1000000 : min(1000000 + 16 * lane, ep);
                int carn = (lane == 0) ? 1000000 : min(1000000 + 16 * lane, en);
                #pragma unroll
                for (int i = 0; i < 16; i++) {
                    int x = WW - 1 - lane * 16 - i;
                    bool m = (cl[i] == cc);
                    carp = m ? carp + 1 : 0;
                    carn = m ? 0 : carn + 1;
                    dbp[c][x] = (unsigned short)min(carp, 60000);
                    dbn[c][x] = (unsigned short)min(carn, 60000);
                }
            }
            __syncthreads();

            // combine fwd/bwd (1536 px over 256 threads -> 6 each)
            #pragma unroll
            for (int k2 = 0; k2 < 6; k2++) {
                int i2 = k2 * NTHR + tid;
                int c2 = i2 >> 9;
                int x = i2 & (WW - 1);
                unsigned short p = min(dfp[c2][x], dbp[c2][x]);
                unsigned short q = min(dfn[c2][x], dbn[c2][x]);
                gstage[c2][x] = make_ushort2(p, q);
            }
            __syncthreads();

            // coalesced uint4 write-out (384 uint4)
            const uint4* s = reinterpret_cast<const uint4*>(&gstage[0][0]);
            uint4* dg = reinterpret_cast<uint4*>(gpn_buf);
            #pragma unroll
            for (int k2 = 0; k2 < 2; k2++) {
                int i2 = k2 * NTHR + tid;
                if (i2 < 384) {
                    int c2 = i2 >> 7;
                    int j = i2 & 127;
                    dg[((size_t)(n * NCL + c2) * HH + r) * (WW / 4) + j] = s[i2];
                }
            }
            __syncthreads();
        }
    }

    // ===================== Grid barrier =====================
    if (tid == 0) {
        __threadfence();
        atomicAdd(&g_bar, 1u);
        while (*((volatile unsigned int*)&g_bar) < NBLK) { }
        __threadfence();
    }
    __syncthreads();

    // ===================== Phase 2: loss (2 tiles of 2 rows) =================
    double local = 0.0;
    unsigned int (*tile)[6][WW] = (unsigned int(*)[6][WW])raw;  // [3][6][512]
    #pragma unroll 1
    for (int tk = 0; tk < 2; tk++) {
        const int t = bid + NBLK * tk;        // 0..511
        const int n = t >> 8;
        const int r0 = (t & 255) * 2;
        __syncthreads();
        // cooperative tile load: rows clamp(r0-2..r0+3) x 3 classes (2304 uint4)
        {
            const uint4* src = reinterpret_cast<const uint4*>(gpn_buf);
            uint4* dst = reinterpret_cast<uint4*>(raw);
            #pragma unroll
            for (int i = 0; i < 9; i++) {
                int ii = i * NTHR + tid;              // 0..2303
                int ci = ii / 768;
                int rem = ii - ci * 768;
                int k6 = rem >> 7;                    // 0..5
                int j = rem & 127;
                int a = min(max(r0 - 2 + k6, 0), HH - 1);
                dst[ii] = src[((size_t)(n * NCL + ci) * HH + a) * (WW / 4) + j];
            }
        }
        __syncthreads();

        const int r = r0 + (tid >> 7);
        const int x = (tid & 127) * 4;
        const int pix = r * WW + x;

        // softmax probs for classes 1..3, 4 pixels
        float prob[NCL][4];
        {
            float4 lv[NC];
            #pragma unroll
            for (int c = 0; c < NC; c++)
                lv[c] = *reinterpret_cast<const float4*>(
                    logits + (size_t)(n * NC + c) * (HH * WW) + pix);
            #pragma unroll
            for (int j = 0; j < 4; j++) {
                float l0 = (&lv[0].x)[j], l1 = (&lv[1].x)[j];
                float l2 = (&lv[2].x)[j], l3 = (&lv[3].x)[j];
                float mx = fmaxf(fmaxf(l0, l1), fmaxf(l2, l3));
                float e0 = __expf(l0 - mx), e1 = __expf(l1 - mx);
                float e2 = __expf(l2 - mx), e3 = __expf(l3 - mx);
                float inv = 1.0f / (e0 + e1 + e2 + e3);
                prob[0][j] = e1 * inv;
                prob[1][j] = e2 * inv;
                prob[2][j] = e3 * inv;
            }
        }

        // smem row slots for center and d=1,2 window (all provably in-tile)
        const int kc  = (tid >> 7) + 2;
        const int ka1 = max(r - 1, 0) - r0 + 2, kb1 = min(r + 1, HH - 1) - r0 + 2;
        const int ka2 = max(r - 2, 0) - r0 + 2, kb2 = min(r + 2, HH - 1) - r0 + 2;

        float acc = 0.0f;
        #pragma unroll 1
        for (int ci = 0; ci < NCL; ci++) {
            if (!g_present[n * NCL + ci]) continue;   // uniform per n
            uint4 wc = *reinterpret_cast<const uint4*>(&tile[ci][kc][x]);
            uint4 u1 = *reinterpret_cast<const uint4*>(&tile[ci][ka1][x]);
            uint4 d1 = *reinterpret_cast<const uint4*>(&tile[ci][kb1][x]);
            uint4 u2 = *reinterpret_cast<const uint4*>(&tile[ci][ka2][x]);
            uint4 d2 = *reinterpret_cast<const uint4*>(&tile[ci][kb2][x]);
            unsigned int bp[4], bn[4], bmax = 0u;
            #pragma unroll
            for (int j = 0; j < 4; j++) {
                unsigned int w = (&wc.x)[j];
                unsigned int gp = w & 0xffffu, gn = w >> 16;
                bp[j] = gp * gp; bn[j] = gn * gn;
                unsigned int q;
                q = (&u1.x)[j] & 0xffffu; bp[j] = min(bp[j], q * q + 1u);
                q = (&u1.x)[j] >> 16;     bn[j] = min(bn[j], q * q + 1u);
                q = (&d1.x)[j] & 0xffffu; bp[j] = min(bp[j], q * q + 1u);
                q = (&d1.x)[j] >> 16;     bn[j] = min(bn[j], q * q + 1u);
                q = (&u2.x)[j] & 0xffffu; bp[j] = min(bp[j], q * q + 4u);
                q = (&u2.x)[j] >> 16;     bn[j] = min(bn[j], q * q + 4u);
                q = (&d2.x)[j] & 0xffffu; bp[j] = min(bp[j], q * q + 4u);
                q = (&d2.x)[j] >> 16;     bn[j] = min(bn[j], q * q + 4u);
                bmax = max(bmax, max(bp[j], bn[j]));
            }
            // rare serial tail from gmem, d >= 3 (clamped rows dominated)
            const unsigned int* col = gpn_buf + ((size_t)(n * NCL + ci) * HH) * WW + x;
            #pragma unroll 1
            for (int d = 3; (unsigned int)(d * d) < bmax; ++d) {
                uint4 wu = *reinterpret_cast<const uint4*>(col + max(r - d, 0) * WW);
                uint4 wd = *reinterpret_cast<const uint4*>(col + min(r + d, HH - 1) * WW);
                unsigned int dd = (unsigned int)(d * d);
                bmax = 0u;
                #pragma unroll
                for (int j = 0; j < 4; j++) {
                    unsigned int q;
                    q = (&wu.x)[j] & 0xffffu; bp[j] = min(bp[j], q * q + dd);
                    q = (&wu.x)[j] >> 16;     bn[j] = min(bn[j], q * q + dd);
                    q = (&wd.x)[j] & 0xffffu; bp[j] = min(bp[j], q * q + dd);
                    q = (&wd.x)[j] >> 16;     bn[j] = min(bn[j], q * q + dd);
                    bmax = max(bmax, max(bp[j], bn[j]));
                }
            }
            #pragma unroll
            for (int j = 0; j < 4; j++)
                acc += prob[ci][j] * (sqrtf((float)bn[j]) - sqrtf((float)bp[j]));
        }
        local += (double)acc;
    }

    // ===================== block reduce + finalize =====================
    #pragma unroll
    for (int off = 16; off > 0; off >>= 1)
        local += __shfl_down_sync(FULL, local, off);
    if (lane == 0) warp_sums[warp] = local;
    __syncthreads();
    if (warp == 0) {
        double v = (lane < 8) ? warp_sums[lane] : 0.0;
        #pragma unroll
        for (int off = 4; off > 0; off >>= 1)
            v += __shfl_down_sync(FULL, v, off);
        if (lane == 0) {
            atomicAdd(&g_acc, v);
            __threadfence();
            unsigned int c = atomicAdd(&g_count, 1u);
            is_last = (c == NBLK - 1);
        }
    }
    __syncthreads();
    // Last block finalizes and restores ALL device state (deterministic replay)
    if (is_last) {
        if (tid == 0) {
            __threadfence();
            double total = g_acc;
            // mean over N*C*H*W = 2*4*512*512 = 2^21 elements
            out[0] = (float)(total * (1.0 / 2097152.0));
            g_acc = 0.0;
            g_count = 0u;
            g_bar = 0u;
        }
        if (tid < NPRES) g_present[tid] = 0;
    }
}

extern "C" void kernel_launch(void* const* d_in, const int* in_sizes, int n_in,
                              void* d_out, int out_size) {
    const float* logits = (const float*)d_in[0];     // [2,4,512,512] fp32
    const int* tgt_words = (const int*)d_in[1];      // [2,512,512] int32 or int64
    float* out = (float*)d_out;

    fused_kernel<<<NBLK, NTHR>>>(logits, tgt_words, out);
}